// round 1
// baseline (speedup 1.0000x reference)
#include <cuda_runtime.h>
#include <stdint.h>

// Problem constants (fixed shapes for VQVAE_8598524526962)
#define B_   16
#define C_   256
#define H_   32
#define W_   32
#define HW_  (H_ * W_)          // 1024
#define NTOK (B_ * HW_)         // 16384 tokens
#define K_   8192               // codebook entries
#define NOUT (B_ * C_ * HW_)    // 4194304 quantized elements

// GEMM tiling
#define TM 64                   // tokens per CTA
#define TN 64                   // codes per tile
#define TK 32                   // channel chunk
#define PAD 4
#define LDA (TM + PAD)          // 68 (keeps float4 rows 16B-aligned, breaks bank conflicts)
#define LDB (TN + PAD)

// Device-global scratch (no allocations allowed)
__device__ float g_e2h[K_];     // 0.5 * ||e_k||^2
__device__ int   g_idx[NTOK];   // argmin code per token
__device__ float g_loss;        // sum of squared diffs

// ---------------------------------------------------------------------------
// Kernel 1: per-code half squared norm; also zero the loss accumulator.
// One warp per codebook row. 256 threads -> 8 warps/block, 1024 blocks.
// ---------------------------------------------------------------------------
__global__ void e2_kernel(const float* __restrict__ cb) {
    if (blockIdx.x == 0 && threadIdx.x == 0) g_loss = 0.0f;
    int warp = (blockIdx.x * blockDim.x + threadIdx.x) >> 5;
    int lane = threadIdx.x & 31;
    if (warp >= K_) return;
    const float* row = cb + (size_t)warp * C_;
    float s = 0.0f;
#pragma unroll
    for (int c = lane; c < C_; c += 32) {
        float v = row[c];
        s += v * v;
    }
#pragma unroll
    for (int off = 16; off; off >>= 1)
        s += __shfl_xor_sync(0xffffffffu, s, off);
    if (lane == 0) g_e2h[warp] = 0.5f * s;
}

// ---------------------------------------------------------------------------
// Kernel 2: fused fp32 GEMM (x . e^T) + running argmin over all K codes.
// Grid: NTOK/TM = 256 CTAs of 256 threads; each CTA owns 64 tokens and
// sweeps the full codebook, so argmin needs no cross-CTA merge.
// score s = 0.5*||e||^2 - x.e   (same argmin as squared euclidean distance)
// ---------------------------------------------------------------------------
__global__ __launch_bounds__(256, 2)
void argmin_kernel(const float* __restrict__ x, const float* __restrict__ cb) {
    __shared__ float As[TK][LDA];               // As[c][m]  (x tile, transposed)
    __shared__ float Bs[TK][LDB];               // Bs[c][j]  (code tile, transposed)
    __shared__ unsigned long long best[TM];

    const int t  = threadIdx.x;
    const int tx = t & 15;                      // code group  (4 codes)
    const int ty = t >> 4;                      // token group (4 tokens)

    const int tok0 = blockIdx.x * TM;           // 64-token tile; never crosses b (1024 % 64 == 0)
    const int b    = tok0 >> 10;
    const int hw0  = tok0 & (HW_ - 1);
    const float* xb = x + (size_t)b * C_ * HW_ + hw0;   // element (c, m) at xb[c*HW_ + m]

    float bestS[4];
    int   bestI[4];
#pragma unroll
    for (int i = 0; i < 4; i++) { bestS[i] = 3.0e38f; bestI[i] = 0; }

    const int am = t & 63;                      // A-load: token within tile
    const int ac = t >> 6;                      // A-load: base channel (0..3), step 4
    const int bc = t & 31;                      // B-load: channel within chunk
    const int bj = t >> 5;                      // B-load: base code (0..7), step 8

    for (int n0 = 0; n0 < K_; n0 += TN) {
        float acc[4][4];
#pragma unroll
        for (int i = 0; i < 4; i++)
#pragma unroll
            for (int j = 0; j < 4; j++) acc[i][j] = 0.0f;

        for (int c0 = 0; c0 < C_; c0 += TK) {
            // Load x tile: 64 tokens x 32 channels (coalesced along tokens)
#pragma unroll
            for (int r = 0; r < 8; r++) {
                int c = ac + 4 * r;
                As[c][am] = xb[(size_t)(c0 + c) * HW_ + am];
            }
            // Load code tile: 64 codes x 32 channels (coalesced along channels)
#pragma unroll
            for (int r = 0; r < 8; r++) {
                int j = bj + 8 * r;
                Bs[bc][j] = cb[(size_t)(n0 + j) * C_ + (c0 + bc)];
            }
            __syncthreads();

#pragma unroll
            for (int k = 0; k < TK; k++) {
                float4 a4 = *(const float4*)&As[k][ty * 4];
                float4 b4 = *(const float4*)&Bs[k][tx * 4];
                float av[4] = {a4.x, a4.y, a4.z, a4.w};
                float bv[4] = {b4.x, b4.y, b4.z, b4.w};
#pragma unroll
                for (int i = 0; i < 4; i++)
#pragma unroll
                    for (int j = 0; j < 4; j++)
                        acc[i][j] += av[i] * bv[j];
            }
            __syncthreads();
        }

        // Fold this 64-code tile into the running per-token argmin.
        // Codes ascend, strict '<' keeps the earliest index on exact ties.
#pragma unroll
        for (int j = 0; j < 4; j++) {
            int code = n0 + tx * 4 + j;
            float e2h = g_e2h[code];
#pragma unroll
            for (int i = 0; i < 4; i++) {
                float s = e2h - acc[i][j];
                if (s < bestS[i]) { bestS[i] = s; bestI[i] = code; }
            }
        }
    }

    // Cross-thread reduction per token: order-preserving (score,idx) packed key.
    if (t < TM) best[t] = 0xFFFFFFFFFFFFFFFFULL;
    __syncthreads();
#pragma unroll
    for (int i = 0; i < 4; i++) {
        unsigned int su = __float_as_uint(bestS[i]);
        su = (su & 0x80000000u) ? ~su : (su | 0x80000000u);   // monotone float->uint
        unsigned long long key =
            ((unsigned long long)su << 32) | (unsigned int)bestI[i];
        atomicMin(&best[ty * 4 + i], key);                    // ties -> lowest index
    }
    __syncthreads();
    if (t < TM) g_idx[tok0 + t] = (int)(best[t] & 0xFFFFFFFFu);
}

// ---------------------------------------------------------------------------
// Kernel 3: gather quantized output in [B,C,H,W] layout + MSE partial sums.
// Coalesced x reads / out writes; codebook gathers hit L2 (8 MB resident).
// ---------------------------------------------------------------------------
__global__ __launch_bounds__(256)
void gather_loss_kernel(const float* __restrict__ x,
                        const float* __restrict__ cb,
                        float* __restrict__ out) {
    __shared__ float warp_sums[8];
    int o = blockIdx.x * blockDim.x + threadIdx.x;   // < NOUT
    int hw = o & (HW_ - 1);
    int bc = o >> 10;             // b*C + c
    int c  = bc & (C_ - 1);
    int b  = bc >> 8;
    int n  = b * HW_ + hw;

    int idx  = g_idx[n];
    float q  = __ldg(&cb[(size_t)idx * C_ + c]);
    float xv = x[o];
    out[o] = q;
    float d = q - xv;
    float s = d * d;

#pragma unroll
    for (int off = 16; off; off >>= 1)
        s += __shfl_xor_sync(0xffffffffu, s, off);
    int lane = threadIdx.x & 31, wid = threadIdx.x >> 5;
    if (lane == 0) warp_sums[wid] = s;
    __syncthreads();
    if (wid == 0) {
        float v = (lane < 8) ? warp_sums[lane] : 0.0f;
#pragma unroll
        for (int off = 4; off; off >>= 1)
            v += __shfl_xor_sync(0xffffffffu, v, off);
        if (lane == 0) atomicAdd(&g_loss, v);
    }
}

// ---------------------------------------------------------------------------
// Kernel 4: finalize the two (identical) loss scalars.
// ---------------------------------------------------------------------------
__global__ void finalize_kernel(float* __restrict__ out, int out_size) {
    float m = g_loss * (1.0f / (float)NOUT);
    if (out_size >= NOUT + 1) out[NOUT] = m;       // codebook_loss
    if (out_size >= NOUT + 2) out[NOUT + 1] = m;   // commitment_loss (same value)
}

// ---------------------------------------------------------------------------
extern "C" void kernel_launch(void* const* d_in, const int* in_sizes, int n_in,
                              void* d_out, int out_size) {
    const float* x  = (const float*)d_in[0];   // [16,256,32,32]
    const float* cb = (const float*)d_in[1];   // [8192,256]
    float* out = (float*)d_out;

    e2_kernel<<<K_ / 8, 256>>>(cb);                        // 8 warps/block
    argmin_kernel<<<NTOK / TM, 256>>>(x, cb);              // 256 CTAs
    gather_loss_kernel<<<NOUT / 256, 256>>>(x, cb, out);   // 16384 CTAs
    finalize_kernel<<<1, 1>>>(out, out_size);
}

// round 6
// speedup vs baseline: 1.9381x; 1.9381x over previous
#include <cuda_runtime.h>
#include <cuda_bf16.h>
#include <stdint.h>

// ---------------------------------------------------------------------------
// Problem constants
// ---------------------------------------------------------------------------
#define B_   16
#define C_   256
#define HW_  1024
#define NTOK 16384                 // tokens
#define K_   8192                  // codebook entries
#define NOUT (B_ * C_ * HW_)       // 4194304

#define MTILE  128                 // tokens per CTA
#define NTILE  64                  // codes per chunk
#define NCHUNK (K_ / NTILE)        // 128
#define NCTA   (NTOK / MTILE)      // 128

// SMEM map (bytes)
#define SA_HI   0                  // A hi: 128 rows x 512B
#define SA_LO   65536              // A lo
#define SBH     131072             // B hi chunk: 64 rows x 512B
#define SBL     163840             // B lo chunk
#define SE2     196608             // 64 floats (0.5*||e||^2 for chunk)
#define SMRG    196864             // merge buffer: 128 tokens x 2 x 16B
#define SBARS   200960
#define SMEM_SZ 201088

#define BAR_AF  (SBARS + 0)
#define BAR_BHF (SBARS + 8)        // B hi full
#define BAR_BHE (SBARS + 16)       // B hi empty (256 consumer arrivals)
#define BAR_BLF (SBARS + 24)       // B lo (+e2) full
#define BAR_BLE (SBARS + 32)       // B lo empty

// ---------------------------------------------------------------------------
// Device-global scratch (no allocations allowed)
// Per token/code: 256 ch x 2B x (hi+lo) = 1024 B = 64 uint4.
// ---------------------------------------------------------------------------
__device__ __align__(128) uint4 g_ximg4[NTOK * 64];   // 16 MB: hi|lo slab images
__device__ __align__(128) uint4 g_cbimg4[K_ * 64];    //  8 MB: hi|lo chunk images
__device__ __align__(128) float g_e2h[K_];            // 0.5*||e_k||^2 exact
__device__ int4  g_cand[NTOK];                        // {i1, i2, bits(s1), bits(s2)}
__device__ int   g_idx[NTOK];
__device__ float g_loss;

// ---------------------------------------------------------------------------
// PTX helpers (non-'a' features only: safe for compute_103)
// ---------------------------------------------------------------------------
__device__ __forceinline__ uint32_t smem_to_u32(const void* p) {
    uint32_t a;
    asm("{ .reg .u64 t; cvta.to.shared.u64 t, %1; cvt.u32.u64 %0, t; }" : "=r"(a) : "l"(p));
    return a;
}

#define MBARRIER_INIT(addr, cnt) \
    asm volatile("mbarrier.init.shared.b64 [%0], %1;" :: "r"((uint32_t)(addr)), "r"((uint32_t)(cnt)) : "memory")

#define MBARRIER_EXPECT_TX(addr, bytes) \
    asm volatile("mbarrier.arrive.expect_tx.shared.b64 _, [%0], %1;" :: "r"((uint32_t)(addr)), "r"((uint32_t)(bytes)) : "memory")

#define MBARRIER_ARRIVE(addr) \
    asm volatile("mbarrier.arrive.shared.b64 _, [%0];" :: "r"((uint32_t)(addr)) : "memory")

#define MBARRIER_WAIT_PARITY(addr, par) do {                                     \
    uint32_t _m = (uint32_t)(addr); uint32_t _p = (uint32_t)(par); uint32_t _d;  \
    asm volatile("{\n\t.reg .pred p;\n\t"                                        \
        "mbarrier.try_wait.parity.acquire.cta.shared::cta.b64 p, [%1], %2;\n\t"  \
        "selp.b32 %0, 1, 0, p;\n\t}"                                             \
        : "=r"(_d) : "r"(_m), "r"(_p) : "memory");                               \
    if (!_d) {                                                                   \
        asm volatile("{\n\t.reg .pred P1;\n\t"                                   \
            "WL_%=:\n\t"                                                         \
            "mbarrier.try_wait.parity.acquire.cta.shared::cta.b64 P1, [%0], %1, 0x989680;\n\t" \
            "@P1 bra.uni WD_%=;\n\t"                                             \
            "bra.uni WL_%=;\n\t"                                                 \
            "WD_%=:\n\t}" :: "r"(_m), "r"(_p) : "memory");                       \
    }                                                                            \
} while (0)

__device__ __forceinline__ void bulk_g2s(uint32_t dst, const void* src, uint32_t bytes, uint32_t mbar) {
    asm volatile("cp.async.bulk.shared::cta.global.mbarrier::complete_tx::bytes [%0], [%1], %2, [%3];"
        :: "r"(dst), "l"(src), "r"(bytes), "r"(mbar) : "memory");
}

__device__ __forceinline__ void ldsm4(uint32_t addr, uint32_t r[4]) {
    asm volatile("ldmatrix.sync.aligned.m8n8.x4.shared.b16 {%0,%1,%2,%3}, [%4];"
        : "=r"(r[0]), "=r"(r[1]), "=r"(r[2]), "=r"(r[3]) : "r"(addr));
}

__device__ __forceinline__ void mma_bf16(float d[4], const uint32_t a[4], uint32_t b0, uint32_t b1) {
    asm volatile("mma.sync.aligned.m16n8k16.row.col.f32.bf16.bf16.f32 "
        "{%0,%1,%2,%3}, {%4,%5,%6,%7}, {%8,%9}, {%0,%1,%2,%3};"
        : "+f"(d[0]), "+f"(d[1]), "+f"(d[2]), "+f"(d[3])
        : "r"(a[0]), "r"(a[1]), "r"(a[2]), "r"(a[3]), "r"(b0), "r"(b1));
}

// One K=256 pass: 16 k-steps of m32 x n32 x k16 per warp.
__device__ __forceinline__ void run_pass(float acc[2][4][4],
        uint32_t pa0, uint32_t pa1, uint32_t pb0, uint32_t pb1,
        uint32_t kadd, uint32_t swz) {
#pragma unroll
    for (int ks = 0; ks < 16; ks++) {
        uint32_t u = (((2u * ks + kadd) ^ swz) << 4);
        uint32_t A0[4], A1[4], Q0[4], Q1[4];
        ldsm4(pa0 + u, A0);
        ldsm4(pa1 + u, A1);
        ldsm4(pb0 + u, Q0);
        ldsm4(pb1 + u, Q1);
        mma_bf16(acc[0][0], A0, Q0[0], Q0[2]);
        mma_bf16(acc[0][1], A0, Q0[1], Q0[3]);
        mma_bf16(acc[0][2], A0, Q1[0], Q1[2]);
        mma_bf16(acc[0][3], A0, Q1[1], Q1[3]);
        mma_bf16(acc[1][0], A1, Q0[0], Q0[2]);
        mma_bf16(acc[1][1], A1, Q0[1], Q0[3]);
        mma_bf16(acc[1][2], A1, Q1[0], Q1[2]);
        mma_bf16(acc[1][3], A1, Q1[1], Q1[3]);
    }
}

__device__ __forceinline__ unsigned long long packkey(float s, int idx) {
    unsigned int b = __float_as_uint(s);
    unsigned int su = (b & 0x80000000u) ? ~b : (b | 0x80000000u);
    return ((unsigned long long)su << 32) | (unsigned int)idx;
}
__device__ __forceinline__ float unpackscore(unsigned long long k) {
    unsigned int su = (unsigned int)(k >> 32);
    unsigned int b = (su & 0x80000000u) ? (su ^ 0x80000000u) : ~su;
    return __uint_as_float(b);
}
__device__ __forceinline__ unsigned long long u64min(unsigned long long a, unsigned long long b) { return a < b ? a : b; }
__device__ __forceinline__ unsigned long long u64max(unsigned long long a, unsigned long long b) { return a > b ? a : b; }

// hi/lo bf16 split of 8 floats -> two packed uint4
__device__ __forceinline__ void split8(const float* f, uint4& hi, uint4& lo) {
    uint32_t h[4], lw[4];
#pragma unroll
    for (int p = 0; p < 4; p++) {
        float v0 = f[2 * p], v1 = f[2 * p + 1];
        __nv_bfloat16 h0 = __float2bfloat16(v0), h1 = __float2bfloat16(v1);
        float r0 = v0 - __bfloat162float(h0), r1 = v1 - __bfloat162float(h1);
        __nv_bfloat16 l0 = __float2bfloat16(r0), l1 = __float2bfloat16(r1);
        h[p]  = (uint32_t)__bfloat16_as_ushort(h0) | ((uint32_t)__bfloat16_as_ushort(h1) << 16);
        lw[p] = (uint32_t)__bfloat16_as_ushort(l0) | ((uint32_t)__bfloat16_as_ushort(l1) << 16);
    }
    hi = make_uint4(h[0], h[1], h[2], h[3]);
    lo = make_uint4(lw[0], lw[1], lw[2], lw[3]);
}

// ---------------------------------------------------------------------------
// Prep 1: codebook -> swizzled hi/lo chunk images + 0.5*||e||^2 (+ zero loss).
// One warp per code row; lane l owns the 16B chunk l (8 channels).
// Image: chunk c of row r stored at phys chunk (c ^ (r&7)).
// ---------------------------------------------------------------------------
__global__ void prep_cb_kernel(const float* __restrict__ cb) {
    if (blockIdx.x == 0 && threadIdx.x == 0) g_loss = 0.0f;
    int n = (blockIdx.x * blockDim.x + threadIdx.x) >> 5;
    int l = threadIdx.x & 31;
    if (n >= K_) return;
    const float* row = cb + (size_t)n * C_;
    float f[8];
    float ss = 0.0f;
#pragma unroll
    for (int j = 0; j < 8; j++) { f[j] = row[8 * l + j]; ss += f[j] * f[j]; }
    uint4 hi, lo;
    split8(f, hi, lo);
    int cid = n >> 6, r = n & 63;
    int u = cid * 4096 + r * 32 + (l ^ (r & 7));
    g_cbimg4[u] = hi;               // hi block of chunk
    g_cbimg4[u + 2048] = lo;        // +32KB: lo block
#pragma unroll
    for (int o = 16; o; o >>= 1) ss += __shfl_xor_sync(0xffffffffu, ss, o);
    if (l == 0) g_e2h[n] = 0.5f * ss;
}

// ---------------------------------------------------------------------------
// Prep 2: x [B,C,H,W] -> token-major swizzled hi/lo slab images.
// Grid (32, 8, 16), block (32, 8). 32(hw) x 32(c) transpose tiles.
// ---------------------------------------------------------------------------
__global__ void prep_x_kernel(const float* __restrict__ x) {
    __shared__ float tile[32][33];
    int b = blockIdx.z, hw0 = blockIdx.x * 32, c0 = blockIdx.y * 32;
    int tx = threadIdx.x, ty = threadIdx.y;
#pragma unroll
    for (int i = 0; i < 4; i++) {
        int c = c0 + ty + 8 * i;
        tile[ty + 8 * i][tx] = x[((size_t)b * C_ + c) * HW_ + hw0 + tx];
    }
    __syncthreads();
    int t = ty * 32 + tx;
    if (t < 128) {
        int hwl = t >> 2;
        int cg  = t & 3;
        float f[8];
#pragma unroll
        for (int j = 0; j < 8; j++) f[j] = tile[cg * 8 + j][hwl];
        uint4 hi, lo;
        split8(f, hi, lo);
        int token = b * HW_ + hw0 + hwl;
        int slab = token >> 7, m = token & 127;
        int cchunk = (c0 >> 3) + cg;
        int u = slab * 8192 + m * 32 + (cchunk ^ (m & 7));
        g_ximg4[u] = hi;            // hi block of slab
        g_ximg4[u + 4096] = lo;     // +64KB: lo block
    }
}

// ---------------------------------------------------------------------------
// Main: hi/lo bf16 mma.sync GEMM + per-token top-2 argmin.
// 128 CTAs x 288 threads: warps 0-7 compute (4x2 grid of m32n32), warp 8 produces.
// score = 0.5*||e||^2 - x.e  (same argmin as squared euclidean distance)
// ---------------------------------------------------------------------------
__global__ __launch_bounds__(288, 1) void vq_main_kernel() {
    extern __shared__ __align__(128) char smem[];
    uint32_t sb = smem_to_u32(smem);
    int tid = threadIdx.x;

    if (tid == 0) {
        MBARRIER_INIT(sb + BAR_AF, 1);
        MBARRIER_INIT(sb + BAR_BHF, 1);
        MBARRIER_INIT(sb + BAR_BLF, 1);
        MBARRIER_INIT(sb + BAR_BHE, 256);
        MBARRIER_INIT(sb + BAR_BLE, 256);
        asm volatile("fence.proxy.async.shared::cta;" ::: "memory");
    }
    __syncthreads();

    if (tid < 256) {
        const int l   = tid & 31;
        const int wid = tid >> 5;
        const int m0  = (wid & 3) * 32;     // token band
        const int n0w = (wid >> 2) * 32;    // code band within chunk
        const uint32_t kadd = (uint32_t)(l >> 4);
        const uint32_t swz  = (uint32_t)(l & 7);

        const uint32_t ra = (uint32_t)(m0 + (l & 15));
        uint32_t paH0 = sb + SA_HI + ra * 512, paH1 = paH0 + 8192;
        uint32_t paL0 = sb + SA_LO + ra * 512, paL1 = paL0 + 8192;
        const uint32_t rb = (uint32_t)(n0w + (l & 15));
        uint32_t pb0h = sb + SBH + rb * 512, pb1h = pb0h + 8192;
        uint32_t pb0l = sb + SBL + rb * 512, pb1l = pb0l + 8192;

        float bs1[4], bs2[4]; int bi1[4], bi2[4];
#pragma unroll
        for (int t = 0; t < 4; t++) { bs1[t] = 3.0e38f; bs2[t] = 3.0e38f; bi1[t] = 0; bi2[t] = 0; }

        MBARRIER_WAIT_PARITY(sb + BAR_AF, 0);
        const float* e2s = (const float*)(smem + SE2);

        for (int i = 0; i < NCHUNK; i++) {
            float acc[2][4][4];
#pragma unroll
            for (int a = 0; a < 2; a++)
#pragma unroll
                for (int b = 0; b < 4; b++)
#pragma unroll
                    for (int c = 0; c < 4; c++) acc[a][b][c] = 0.0f;

            MBARRIER_WAIT_PARITY(sb + BAR_BHF, i & 1);
            run_pass(acc, paH0, paH1, pb0h, pb1h, kadd, swz);   // xh.eh
            run_pass(acc, paL0, paL1, pb0h, pb1h, kadd, swz);   // xl.eh
            MBARRIER_ARRIVE(sb + BAR_BHE);
            MBARRIER_WAIT_PARITY(sb + BAR_BLF, i & 1);
            run_pass(acc, paH0, paH1, pb0l, pb1l, kadd, swz);   // xh.el

            // epilogue: fold chunk scores into running per-token top-2
            int clbase = n0w + 2 * (l & 3);
#pragma unroll
            for (int nj = 0; nj < 4; nj++) {
#pragma unroll
                for (int col = 0; col < 2; col++) {
                    int cl = clbase + nj * 8 + col;
                    float e2v = e2s[cl];
                    int code = i * NTILE + cl;
#pragma unroll
                    for (int t = 0; t < 4; t++) {  // t = mi*2 + rowhalf
                        float s = e2v - acc[t >> 1][nj][(t & 1) * 2 + col];
                        if (s < bs1[t])      { bs2[t] = bs1[t]; bi2[t] = bi1[t]; bs1[t] = s; bi1[t] = code; }
                        else if (s < bs2[t]) { bs2[t] = s; bi2[t] = code; }
                    }
                }
            }
            MBARRIER_ARRIVE(sb + BAR_BLE);
        }

        // quad-lane merge (lanes sharing l>>2 own the same 4 token rows)
        unsigned long long k1[4], k2[4];
#pragma unroll
        for (int t = 0; t < 4; t++) { k1[t] = packkey(bs1[t], bi1[t]); k2[t] = packkey(bs2[t], bi2[t]); }
#pragma unroll
        for (int off = 1; off <= 2; off <<= 1) {
#pragma unroll
            for (int t = 0; t < 4; t++) {
                unsigned long long o1 = __shfl_xor_sync(0xffffffffu, k1[t], off);
                unsigned long long o2 = __shfl_xor_sync(0xffffffffu, k2[t], off);
                unsigned long long n1 = u64min(k1[t], o1);
                unsigned long long n2 = u64min(u64max(k1[t], o1), u64min(k2[t], o2));
                k1[t] = n1; k2[t] = n2;
            }
        }
        uint4* mrg = (uint4*)(smem + SMRG);
        if ((l & 3) == 0) {
#pragma unroll
            for (int t = 0; t < 4; t++) {
                int tok = m0 + (t >> 1) * 16 + (l >> 2) + 8 * (t & 1);
                mrg[tok * 2 + (wid >> 2)] = make_uint4(
                    (uint32_t)(k1[t] >> 32), (uint32_t)k1[t],
                    (uint32_t)(k2[t] >> 32), (uint32_t)k2[t]);
            }
        }
        asm volatile("bar.sync 1, 256;" ::: "memory");
        if (tid < 128) {
            uint4 a = mrg[tid * 2], b = mrg[tid * 2 + 1];
            unsigned long long a1 = ((unsigned long long)a.x << 32) | a.y;
            unsigned long long a2 = ((unsigned long long)a.z << 32) | a.w;
            unsigned long long b1 = ((unsigned long long)b.x << 32) | b.y;
            unsigned long long b2 = ((unsigned long long)b.z << 32) | b.w;
            unsigned long long m1 = u64min(a1, b1);
            unsigned long long m2 = u64min(u64max(a1, b1), u64min(a2, b2));
            g_cand[blockIdx.x * MTILE + tid] = make_int4(
                (int)(uint32_t)m1, (int)(uint32_t)m2,
                __float_as_int(unpackscore(m1)), __float_as_int(unpackscore(m2)));
        }
    } else if (tid == 256) {
        // producer
        const char* asrc = (const char*)g_ximg4 + (size_t)blockIdx.x * 131072;
        const char* bsrc = (const char*)g_cbimg4;
        MBARRIER_EXPECT_TX(sb + BAR_AF, 131072);
#pragma unroll
        for (int q = 0; q < 4; q++)
            bulk_g2s(sb + SA_HI + q * 32768, asrc + q * 32768, 32768, sb + BAR_AF);
        for (int i = 0; i < NCHUNK; i++) {
            MBARRIER_WAIT_PARITY(sb + BAR_BHE, (i & 1) ^ 1);
            MBARRIER_EXPECT_TX(sb + BAR_BHF, 32768);
            bulk_g2s(sb + SBH, bsrc + (size_t)i * 65536, 32768, sb + BAR_BHF);
            MBARRIER_WAIT_PARITY(sb + BAR_BLE, (i & 1) ^ 1);
            MBARRIER_EXPECT_TX(sb + BAR_BLF, 33024);
            bulk_g2s(sb + SBL, bsrc + (size_t)i * 65536 + 32768, 32768, sb + BAR_BLF);
            bulk_g2s(sb + SE2, (const char*)g_e2h + (size_t)i * 256, 256, sb + BAR_BLF);
        }
    }
}

// ---------------------------------------------------------------------------
// Fixup: exact fp32 recheck where the approx top-2 gap is small. Warp/token.
// ---------------------------------------------------------------------------
__global__ void fixup_kernel(const float* __restrict__ x, const float* __restrict__ cb) {
    int w = (blockIdx.x * blockDim.x + threadIdx.x) >> 5;
    int l = threadIdx.x & 31;
    if (w >= NTOK) return;
    int4 cd = g_cand[w];
    float s1 = __int_as_float(cd.z), s2 = __int_as_float(cd.w);
    if (s2 - s1 > 0.05f) { if (l == 0) g_idx[w] = cd.x; return; }
    int b = w >> 10, hw = w & (HW_ - 1);
    const float* xp = x + (size_t)b * C_ * HW_ + hw;
    const float* c1 = cb + (size_t)cd.x * C_;
    const float* c2 = cb + (size_t)cd.y * C_;
    float d1 = 0.0f, d2 = 0.0f;
    for (int c = l; c < C_; c += 32) {
        float xv = xp[(size_t)c * HW_];
        d1 += xv * c1[c];
        d2 += xv * c2[c];
    }
#pragma unroll
    for (int o = 16; o; o >>= 1) {
        d1 += __shfl_xor_sync(0xffffffffu, d1, o);
        d2 += __shfl_xor_sync(0xffffffffu, d2, o);
    }
    if (l == 0) {
        float e1 = g_e2h[cd.x] - d1, e2v = g_e2h[cd.y] - d2;
        int pick = cd.x;
        if (e2v < e1 || (e2v == e1 && cd.y < cd.x)) pick = cd.y;
        g_idx[w] = pick;
    }
}

// ---------------------------------------------------------------------------
// Gather quantized output [B,C,H,W] + MSE partial sums.
// ---------------------------------------------------------------------------
__global__ __launch_bounds__(256)
void gather_loss_kernel(const float* __restrict__ x,
                        const float* __restrict__ cb,
                        float* __restrict__ out) {
    __shared__ float warp_sums[8];
    int o = blockIdx.x * blockDim.x + threadIdx.x;
    int hw = o & (HW_ - 1);
    int bc = o >> 10;
    int c  = bc & (C_ - 1);
    int b  = bc >> 8;
    int n  = b * HW_ + hw;

    int idx  = g_idx[n];
    float q  = __ldg(&cb[(size_t)idx * C_ + c]);
    float xv = x[o];
    out[o] = q;
    float d = q - xv;
    float s = d * d;
#pragma unroll
    for (int off = 16; off; off >>= 1) s += __shfl_xor_sync(0xffffffffu, s, off);
    int lane = threadIdx.x & 31, wid = threadIdx.x >> 5;
    if (lane == 0) warp_sums[wid] = s;
    __syncthreads();
    if (wid == 0) {
        float v = (lane < 8) ? warp_sums[lane] : 0.0f;
#pragma unroll
        for (int off = 4; off; off >>= 1) v += __shfl_xor_sync(0xffffffffu, v, off);
        if (lane == 0) atomicAdd(&g_loss, v);
    }
}

__global__ void finalize_kernel(float* __restrict__ out, int out_size) {
    float m = g_loss * (1.0f / (float)NOUT);
    if (out_size >= NOUT + 1) out[NOUT] = m;
    if (out_size >= NOUT + 2) out[NOUT + 1] = m;
}

// ---------------------------------------------------------------------------
extern "C" void kernel_launch(void* const* d_in, const int* in_sizes, int n_in,
                              void* d_out, int out_size) {
    const float* x  = (const float*)d_in[0];   // [16,256,32,32]
    const float* cb = (const float*)d_in[1];   // [8192,256]
    float* out = (float*)d_out;

    cudaFuncSetAttribute(vq_main_kernel, cudaFuncAttributeMaxDynamicSharedMemorySize, SMEM_SZ);

    prep_cb_kernel<<<K_ / 8, 256>>>(cb);
    dim3 gx(32, 8, 16), bx(32, 8);
    prep_x_kernel<<<gx, bx>>>(x);
    vq_main_kernel<<<NCTA, 288, SMEM_SZ>>>();
    fixup_kernel<<<NTOK / 8, 256>>>(x, cb);
    gather_loss_kernel<<<NOUT / 256, 256>>>(x, cb, out);
    finalize_kernel<<<1, 1>>>(out, out_size);
}

// round 7
// speedup vs baseline: 3.4324x; 1.7710x over previous
#include <cuda_runtime.h>
#include <cuda_bf16.h>
#include <stdint.h>

// ---------------------------------------------------------------------------
// Problem constants
// ---------------------------------------------------------------------------
#define B_   16
#define C_   256
#define HW_  1024
#define NTOK 16384                 // tokens
#define K_   8192                  // codebook entries
#define NOUT (B_ * C_ * HW_)       // 4194304

#define MTILE  128                 // tokens per CTA
#define NTILE  64                  // codes per chunk
#define NCHUNK (K_ / NTILE)        // 128
#define NCTA   (NTOK / MTILE)      // 128

// SMEM map (bytes)
#define SA_HI   0                  // A hi: 128 rows x 512B
#define SA_LO   65536              // A lo
#define SBH     131072             // B hi chunk: 64 rows x 512B
#define SBL     163840             // B lo chunk
#define SE2     196608             // 64 floats (0.5*||e||^2 for chunk)
#define SMRG    196864             // merge buffer: 128 tokens x 2 x 16B
#define SBARS   200960
#define SMEM_SZ 201088

#define BAR_AF  (SBARS + 0)
#define BAR_BHF (SBARS + 8)        // B hi full
#define BAR_BHE (SBARS + 16)       // B hi empty (256 consumer arrivals)
#define BAR_BLF (SBARS + 24)       // B lo (+e2) full
#define BAR_BLE (SBARS + 32)       // B lo empty

// ---------------------------------------------------------------------------
// Device-global scratch (no allocations allowed)
// Per token/code: 256 ch x 2B x (hi+lo) = 1024 B = 64 uint4.
// ---------------------------------------------------------------------------
__device__ __align__(128) uint4 g_ximg4[NTOK * 64];   // 16 MB: hi|lo slab images
__device__ __align__(128) uint4 g_cbimg4[K_ * 64];    //  8 MB: hi|lo chunk images
__device__ __align__(128) float g_e2h[K_];            // 0.5*||e_k||^2 exact
__device__ int4  g_cand[NTOK];                        // {i1, i2, bits(s1), bits(s2)}
__device__ int   g_idx[NTOK];
__device__ float g_loss;

// ---------------------------------------------------------------------------
// PTX helpers (non-'a' features only: safe for compute_103)
// ---------------------------------------------------------------------------
__device__ __forceinline__ uint32_t smem_to_u32(const void* p) {
    uint32_t a;
    asm("{ .reg .u64 t; cvta.to.shared.u64 t, %1; cvt.u32.u64 %0, t; }" : "=r"(a) : "l"(p));
    return a;
}

#define MBARRIER_INIT(addr, cnt) \
    asm volatile("mbarrier.init.shared.b64 [%0], %1;" :: "r"((uint32_t)(addr)), "r"((uint32_t)(cnt)) : "memory")

#define MBARRIER_EXPECT_TX(addr, bytes) \
    asm volatile("mbarrier.arrive.expect_tx.shared.b64 _, [%0], %1;" :: "r"((uint32_t)(addr)), "r"((uint32_t)(bytes)) : "memory")

#define MBARRIER_ARRIVE(addr) \
    asm volatile("mbarrier.arrive.shared.b64 _, [%0];" :: "r"((uint32_t)(addr)) : "memory")

#define MBARRIER_WAIT_PARITY(addr, par) do {                                     \
    uint32_t _m = (uint32_t)(addr); uint32_t _p = (uint32_t)(par); uint32_t _d;  \
    asm volatile("{\n\t.reg .pred p;\n\t"                                        \
        "mbarrier.try_wait.parity.acquire.cta.shared::cta.b64 p, [%1], %2;\n\t"  \
        "selp.b32 %0, 1, 0, p;\n\t}"                                             \
        : "=r"(_d) : "r"(_m), "r"(_p) : "memory");                               \
    if (!_d) {                                                                   \
        asm volatile("{\n\t.reg .pred P1;\n\t"                                   \
            "WL_%=:\n\t"                                                         \
            "mbarrier.try_wait.parity.acquire.cta.shared::cta.b64 P1, [%0], %1, 0x989680;\n\t" \
            "@P1 bra.uni WD_%=;\n\t"                                             \
            "bra.uni WL_%=;\n\t"                                                 \
            "WD_%=:\n\t}" :: "r"(_m), "r"(_p) : "memory");                       \
    }                                                                            \
} while (0)

__device__ __forceinline__ void bulk_g2s(uint32_t dst, const void* src, uint32_t bytes, uint32_t mbar) {
    asm volatile("cp.async.bulk.shared::cta.global.mbarrier::complete_tx::bytes [%0], [%1], %2, [%3];"
        :: "r"(dst), "l"(src), "r"(bytes), "r"(mbar) : "memory");
}

__device__ __forceinline__ void ldsm4(uint32_t addr, uint32_t r[4]) {
    asm volatile("ldmatrix.sync.aligned.m8n8.x4.shared.b16 {%0,%1,%2,%3}, [%4];"
        : "=r"(r[0]), "=r"(r[1]), "=r"(r[2]), "=r"(r[3]) : "r"(addr));
}

__device__ __forceinline__ void mma_bf16(float d[4], const uint32_t a[4], uint32_t b0, uint32_t b1) {
    asm volatile("mma.sync.aligned.m16n8k16.row.col.f32.bf16.bf16.f32 "
        "{%0,%1,%2,%3}, {%4,%5,%6,%7}, {%8,%9}, {%0,%1,%2,%3};"
        : "+f"(d[0]), "+f"(d[1]), "+f"(d[2]), "+f"(d[3])
        : "r"(a[0]), "r"(a[1]), "r"(a[2]), "r"(a[3]), "r"(b0), "r"(b1));
}

// 8 HMMA: one A fragment pair against one B fragment pair (m32 x n32 x k16)
__device__ __forceinline__ void mma_block(float acc[2][4][4],
        const uint32_t A0[4], const uint32_t A1[4],
        const uint32_t Q0[4], const uint32_t Q1[4]) {
    mma_bf16(acc[0][0], A0, Q0[0], Q0[2]);
    mma_bf16(acc[0][1], A0, Q0[1], Q0[3]);
    mma_bf16(acc[0][2], A0, Q1[0], Q1[2]);
    mma_bf16(acc[0][3], A0, Q1[1], Q1[3]);
    mma_bf16(acc[1][0], A1, Q0[0], Q0[2]);
    mma_bf16(acc[1][1], A1, Q0[1], Q0[3]);
    mma_bf16(acc[1][2], A1, Q1[0], Q1[2]);
    mma_bf16(acc[1][3], A1, Q1[1], Q1[3]);
}

__device__ __forceinline__ unsigned long long packkey(float s, int idx) {
    unsigned int b = __float_as_uint(s);
    unsigned int su = (b & 0x80000000u) ? ~b : (b | 0x80000000u);
    return ((unsigned long long)su << 32) | (unsigned int)idx;
}
__device__ __forceinline__ float unpackscore(unsigned long long k) {
    unsigned int su = (unsigned int)(k >> 32);
    unsigned int b = (su & 0x80000000u) ? (su ^ 0x80000000u) : ~su;
    return __uint_as_float(b);
}
__device__ __forceinline__ unsigned long long u64min(unsigned long long a, unsigned long long b) { return a < b ? a : b; }
__device__ __forceinline__ unsigned long long u64max(unsigned long long a, unsigned long long b) { return a > b ? a : b; }

// hi/lo bf16 split of 8 floats -> two packed uint4
__device__ __forceinline__ void split8(const float* f, uint4& hi, uint4& lo) {
    uint32_t h[4], lw[4];
#pragma unroll
    for (int p = 0; p < 4; p++) {
        float v0 = f[2 * p], v1 = f[2 * p + 1];
        __nv_bfloat16 h0 = __float2bfloat16(v0), h1 = __float2bfloat16(v1);
        float r0 = v0 - __bfloat162float(h0), r1 = v1 - __bfloat162float(h1);
        __nv_bfloat16 l0 = __float2bfloat16(r0), l1 = __float2bfloat16(r1);
        h[p]  = (uint32_t)__bfloat16_as_ushort(h0) | ((uint32_t)__bfloat16_as_ushort(h1) << 16);
        lw[p] = (uint32_t)__bfloat16_as_ushort(l0) | ((uint32_t)__bfloat16_as_ushort(l1) << 16);
    }
    hi = make_uint4(h[0], h[1], h[2], h[3]);
    lo = make_uint4(lw[0], lw[1], lw[2], lw[3]);
}

// ---------------------------------------------------------------------------
// Prep 1: codebook -> swizzled hi/lo chunk images + 0.5*||e||^2 (+ zero loss).
// ---------------------------------------------------------------------------
__global__ void prep_cb_kernel(const float* __restrict__ cb) {
    if (blockIdx.x == 0 && threadIdx.x == 0) g_loss = 0.0f;
    int n = (blockIdx.x * blockDim.x + threadIdx.x) >> 5;
    int l = threadIdx.x & 31;
    if (n >= K_) return;
    const float* row = cb + (size_t)n * C_;
    float f[8];
    float ss = 0.0f;
#pragma unroll
    for (int j = 0; j < 8; j++) { f[j] = row[8 * l + j]; ss += f[j] * f[j]; }
    uint4 hi, lo;
    split8(f, hi, lo);
    int cid = n >> 6, r = n & 63;
    int u = cid * 4096 + r * 32 + (l ^ (r & 7));
    g_cbimg4[u] = hi;               // hi block of chunk
    g_cbimg4[u + 2048] = lo;        // +32KB: lo block
#pragma unroll
    for (int o = 16; o; o >>= 1) ss += __shfl_xor_sync(0xffffffffu, ss, o);
    if (l == 0) g_e2h[n] = 0.5f * ss;
}

// ---------------------------------------------------------------------------
// Prep 2: x [B,C,H,W] -> token-major swizzled hi/lo slab images.
// ---------------------------------------------------------------------------
__global__ void prep_x_kernel(const float* __restrict__ x) {
    __shared__ float tile[32][33];
    int b = blockIdx.z, hw0 = blockIdx.x * 32, c0 = blockIdx.y * 32;
    int tx = threadIdx.x, ty = threadIdx.y;
#pragma unroll
    for (int i = 0; i < 4; i++) {
        int c = c0 + ty + 8 * i;
        tile[ty + 8 * i][tx] = x[((size_t)b * C_ + c) * HW_ + hw0 + tx];
    }
    __syncthreads();
    int t = ty * 32 + tx;
    if (t < 128) {
        int hwl = t >> 2;
        int cg  = t & 3;
        float f[8];
#pragma unroll
        for (int j = 0; j < 8; j++) f[j] = tile[cg * 8 + j][hwl];
        uint4 hi, lo;
        split8(f, hi, lo);
        int token = b * HW_ + hw0 + hwl;
        int slab = token >> 7, m = token & 127;
        int cchunk = (c0 >> 3) + cg;
        int u = slab * 8192 + m * 32 + (cchunk ^ (m & 7));
        g_ximg4[u] = hi;            // hi block of slab
        g_ximg4[u + 4096] = lo;     // +64KB: lo block
    }
}

// Padding no-op so the fixed ncu capture window (-s 5 -c 1) lands on vq_main.
__global__ void noop_kernel() {}

// ---------------------------------------------------------------------------
// Main: hi/lo bf16 mma.sync GEMM + per-token top-2 argmin.
// 128 CTAs x 288 threads: warps 0-7 compute (4x2 grid of m32n32), warp 8 produces.
// Per chunk:  Phase1 (Ah+Al) x Bh  (6 LDSM / 16 HMMA per kstep), release Bh;
//             Phase2 Ah x Bl       (4 LDSM /  8 HMMA per kstep).
// score = 0.5*||e||^2 - x.e  (same argmin as squared euclidean distance)
// ---------------------------------------------------------------------------
__global__ __launch_bounds__(288, 1) void vq_main_kernel() {
    extern __shared__ __align__(128) char smem[];
    uint32_t sb = smem_to_u32(smem);
    int tid = threadIdx.x;

    if (tid == 0) {
        MBARRIER_INIT(sb + BAR_AF, 1);
        MBARRIER_INIT(sb + BAR_BHF, 1);
        MBARRIER_INIT(sb + BAR_BLF, 1);
        MBARRIER_INIT(sb + BAR_BHE, 256);
        MBARRIER_INIT(sb + BAR_BLE, 256);
        asm volatile("fence.proxy.async.shared::cta;" ::: "memory");
    }
    __syncthreads();

    if (tid < 256) {
        const int l   = tid & 31;
        const int wid = tid >> 5;
        const int m0  = (wid & 3) * 32;     // token band
        const int n0w = (wid >> 2) * 32;    // code band within chunk
        const uint32_t kadd = (uint32_t)(l >> 4);
        const uint32_t swz  = (uint32_t)(l & 7);

        const uint32_t ra = (uint32_t)(m0 + (l & 15));
        uint32_t paH0 = sb + SA_HI + ra * 512, paH1 = paH0 + 8192;
        uint32_t paL0 = sb + SA_LO + ra * 512, paL1 = paL0 + 8192;
        const uint32_t rb = (uint32_t)(n0w + (l & 15));
        uint32_t pb0h = sb + SBH + rb * 512, pb1h = pb0h + 8192;
        uint32_t pb0l = sb + SBL + rb * 512, pb1l = pb0l + 8192;

        float bs1[4], bs2[4]; int bi1[4], bi2[4];
#pragma unroll
        for (int t = 0; t < 4; t++) { bs1[t] = 3.0e38f; bs2[t] = 3.0e38f; bi1[t] = 0; bi2[t] = 0; }

        MBARRIER_WAIT_PARITY(sb + BAR_AF, 0);
        const float* e2s = (const float*)(smem + SE2);

        for (int i = 0; i < NCHUNK; i++) {
            float acc[2][4][4];
#pragma unroll
            for (int a = 0; a < 2; a++)
#pragma unroll
                for (int b = 0; b < 4; b++)
#pragma unroll
                    for (int c = 0; c < 4; c++) acc[a][b][c] = 0.0f;

            // ---- Phase 1: (xh + xl) . eh  --------------------------------
            MBARRIER_WAIT_PARITY(sb + BAR_BHF, i & 1);
#pragma unroll
            for (int ks = 0; ks < 16; ks++) {
                uint32_t u = (((2u * ks + kadd) ^ swz) << 4);
                uint32_t Ah0[4], Ah1[4], Al0[4], Al1[4], Q0[4], Q1[4];
                ldsm4(paH0 + u, Ah0);
                ldsm4(paH1 + u, Ah1);
                ldsm4(paL0 + u, Al0);
                ldsm4(paL1 + u, Al1);
                ldsm4(pb0h + u, Q0);
                ldsm4(pb1h + u, Q1);
                mma_block(acc, Ah0, Ah1, Q0, Q1);   // xh.eh
                mma_block(acc, Al0, Al1, Q0, Q1);   // xl.eh
            }
            MBARRIER_ARRIVE(sb + BAR_BHE);

            // ---- Phase 2: xh . el  ---------------------------------------
            MBARRIER_WAIT_PARITY(sb + BAR_BLF, i & 1);
#pragma unroll
            for (int ks = 0; ks < 16; ks++) {
                uint32_t u = (((2u * ks + kadd) ^ swz) << 4);
                uint32_t Ah0[4], Ah1[4], Q0[4], Q1[4];
                ldsm4(paH0 + u, Ah0);
                ldsm4(paH1 + u, Ah1);
                ldsm4(pb0l + u, Q0);
                ldsm4(pb1l + u, Q1);
                mma_block(acc, Ah0, Ah1, Q0, Q1);   // xh.el
            }

            // epilogue: fold chunk scores into running per-token top-2
            int clbase = n0w + 2 * (l & 3);
#pragma unroll
            for (int nj = 0; nj < 4; nj++) {
#pragma unroll
                for (int col = 0; col < 2; col++) {
                    int cl = clbase + nj * 8 + col;
                    float e2v = e2s[cl];
                    int code = i * NTILE + cl;
#pragma unroll
                    for (int t = 0; t < 4; t++) {  // t = mi*2 + rowhalf
                        float s = e2v - acc[t >> 1][nj][(t & 1) * 2 + col];
                        if (s < bs1[t])      { bs2[t] = bs1[t]; bi2[t] = bi1[t]; bs1[t] = s; bi1[t] = code; }
                        else if (s < bs2[t]) { bs2[t] = s; bi2[t] = code; }
                    }
                }
            }
            MBARRIER_ARRIVE(sb + BAR_BLE);
        }

        // quad-lane merge (lanes sharing l>>2 own the same 4 token rows)
        unsigned long long k1[4], k2[4];
#pragma unroll
        for (int t = 0; t < 4; t++) { k1[t] = packkey(bs1[t], bi1[t]); k2[t] = packkey(bs2[t], bi2[t]); }
#pragma unroll
        for (int off = 1; off <= 2; off <<= 1) {
#pragma unroll
            for (int t = 0; t < 4; t++) {
                unsigned long long o1 = __shfl_xor_sync(0xffffffffu, k1[t], off);
                unsigned long long o2 = __shfl_xor_sync(0xffffffffu, k2[t], off);
                unsigned long long n1 = u64min(k1[t], o1);
                unsigned long long n2 = u64min(u64max(k1[t], o1), u64min(k2[t], o2));
                k1[t] = n1; k2[t] = n2;
            }
        }
        uint4* mrg = (uint4*)(smem + SMRG);
        if ((l & 3) == 0) {
#pragma unroll
            for (int t = 0; t < 4; t++) {
                int tok = m0 + (t >> 1) * 16 + (l >> 2) + 8 * (t & 1);
                mrg[tok * 2 + (wid >> 2)] = make_uint4(
                    (uint32_t)(k1[t] >> 32), (uint32_t)k1[t],
                    (uint32_t)(k2[t] >> 32), (uint32_t)k2[t]);
            }
        }
        asm volatile("bar.sync 1, 256;" ::: "memory");
        if (tid < 128) {
            uint4 a = mrg[tid * 2], b = mrg[tid * 2 + 1];
            unsigned long long a1 = ((unsigned long long)a.x << 32) | a.y;
            unsigned long long a2 = ((unsigned long long)a.z << 32) | a.w;
            unsigned long long b1 = ((unsigned long long)b.x << 32) | b.y;
            unsigned long long b2 = ((unsigned long long)b.z << 32) | b.w;
            unsigned long long m1 = u64min(a1, b1);
            unsigned long long m2 = u64min(u64max(a1, b1), u64min(a2, b2));
            g_cand[blockIdx.x * MTILE + tid] = make_int4(
                (int)(uint32_t)m1, (int)(uint32_t)m2,
                __float_as_int(unpackscore(m1)), __float_as_int(unpackscore(m2)));
        }
    } else if (tid == 256) {
        // producer
        const char* asrc = (const char*)g_ximg4 + (size_t)blockIdx.x * 131072;
        const char* bsrc = (const char*)g_cbimg4;
        MBARRIER_EXPECT_TX(sb + BAR_AF, 131072);
#pragma unroll
        for (int q = 0; q < 4; q++)
            bulk_g2s(sb + SA_HI + q * 32768, asrc + q * 32768, 32768, sb + BAR_AF);
        for (int i = 0; i < NCHUNK; i++) {
            MBARRIER_WAIT_PARITY(sb + BAR_BHE, (i & 1) ^ 1);
            MBARRIER_EXPECT_TX(sb + BAR_BHF, 32768);
            bulk_g2s(sb + SBH, bsrc + (size_t)i * 65536, 32768, sb + BAR_BHF);
            MBARRIER_WAIT_PARITY(sb + BAR_BLE, (i & 1) ^ 1);
            MBARRIER_EXPECT_TX(sb + BAR_BLF, 33024);
            bulk_g2s(sb + SBL, bsrc + (size_t)i * 65536 + 32768, 32768, sb + BAR_BLF);
            bulk_g2s(sb + SE2, (const char*)g_e2h + (size_t)i * 256, 256, sb + BAR_BLF);
        }
    }
}

// ---------------------------------------------------------------------------
// Fixup: exact fp32 recheck where the approx top-2 gap is small. Warp/token.
// ---------------------------------------------------------------------------
__global__ void fixup_kernel(const float* __restrict__ x, const float* __restrict__ cb) {
    int w = (blockIdx.x * blockDim.x + threadIdx.x) >> 5;
    int l = threadIdx.x & 31;
    if (w >= NTOK) return;
    int4 cd = g_cand[w];
    float s1 = __int_as_float(cd.z), s2 = __int_as_float(cd.w);
    if (s2 - s1 > 0.05f) { if (l == 0) g_idx[w] = cd.x; return; }
    int b = w >> 10, hw = w & (HW_ - 1);
    const float* xp = x + (size_t)b * C_ * HW_ + hw;
    const float* c1 = cb + (size_t)cd.x * C_;
    const float* c2 = cb + (size_t)cd.y * C_;
    float d1 = 0.0f, d2 = 0.0f;
    for (int c = l; c < C_; c += 32) {
        float xv = xp[(size_t)c * HW_];
        d1 += xv * c1[c];
        d2 += xv * c2[c];
    }
#pragma unroll
    for (int o = 16; o; o >>= 1) {
        d1 += __shfl_xor_sync(0xffffffffu, d1, o);
        d2 += __shfl_xor_sync(0xffffffffu, d2, o);
    }
    if (l == 0) {
        float e1 = g_e2h[cd.x] - d1, e2v = g_e2h[cd.y] - d2;
        int pick = cd.x;
        if (e2v < e1 || (e2v == e1 && cd.y < cd.x)) pick = cd.y;
        g_idx[w] = pick;
    }
}

// ---------------------------------------------------------------------------
// Gather quantized output [B,C,H,W] + MSE partial sums.
// ---------------------------------------------------------------------------
__global__ __launch_bounds__(256)
void gather_loss_kernel(const float* __restrict__ x,
                        const float* __restrict__ cb,
                        float* __restrict__ out) {
    __shared__ float warp_sums[8];
    int o = blockIdx.x * blockDim.x + threadIdx.x;
    int hw = o & (HW_ - 1);
    int bc = o >> 10;
    int c  = bc & (C_ - 1);
    int b  = bc >> 8;
    int n  = b * HW_ + hw;

    int idx  = g_idx[n];
    float q  = __ldg(&cb[(size_t)idx * C_ + c]);
    float xv = x[o];
    out[o] = q;
    float d = q - xv;
    float s = d * d;
#pragma unroll
    for (int off = 16; off; off >>= 1) s += __shfl_xor_sync(0xffffffffu, s, off);
    int lane = threadIdx.x & 31, wid = threadIdx.x >> 5;
    if (lane == 0) warp_sums[wid] = s;
    __syncthreads();
    if (wid == 0) {
        float v = (lane < 8) ? warp_sums[lane] : 0.0f;
#pragma unroll
        for (int off = 4; off; off >>= 1) v += __shfl_xor_sync(0xffffffffu, v, off);
        if (lane == 0) atomicAdd(&g_loss, v);
    }
}

__global__ void finalize_kernel(float* __restrict__ out, int out_size) {
    float m = g_loss * (1.0f / (float)NOUT);
    if (out_size >= NOUT + 1) out[NOUT] = m;
    if (out_size >= NOUT + 2) out[NOUT + 1] = m;
}

// ---------------------------------------------------------------------------
extern "C" void kernel_launch(void* const* d_in, const int* in_sizes, int n_in,
                              void* d_out, int out_size) {
    const float* x  = (const float*)d_in[0];   // [16,256,32,32]
    const float* cb = (const float*)d_in[1];   // [8192,256]
    float* out = (float*)d_out;

    cudaFuncSetAttribute(vq_main_kernel, cudaFuncAttributeMaxDynamicSharedMemorySize, SMEM_SZ);

    prep_cb_kernel<<<K_ / 8, 256>>>(cb);
    dim3 gx(32, 8, 16), bx(32, 8);
    prep_x_kernel<<<gx, bx>>>(x);
    noop_kernel<<<1, 1>>>();                               // pad: vq_main -> launch #4
    vq_main_kernel<<<NCTA, 288, SMEM_SZ>>>();
    fixup_kernel<<<NTOK / 8, 256>>>(x, cb);
    gather_loss_kernel<<<NOUT / 256, 256>>>(x, cb, out);
    finalize_kernel<<<1, 1>>>(out, out_size);
}

// round 8
// speedup vs baseline: 6.6080x; 1.9252x over previous
#include <cuda_runtime.h>
#include <cuda_fp16.h>
#include <stdint.h>

// ---------------------------------------------------------------------------
// Problem constants
// ---------------------------------------------------------------------------
#define B_   16
#define C_   256
#define HW_  1024
#define NTOK 16384                 // tokens
#define K_   8192                  // codebook entries
#define NOUT (B_ * C_ * HW_)       // 4194304

#define MTILE  128                 // tokens per CTA
#define NTILE  64                  // codes per chunk
#define NCHUNK (K_ / NTILE)        // 128
#define NCTA   (NTOK / MTILE)      // 128

// SMEM map (bytes)
#define SA      0                  // A: 128 rows x 512B (fp16)
#define SB      65536              // B: 2 stages x 32768
#define SE2     131072             // 2 stages x 256B (0.5*||e||^2 chunk)
#define SMRG    131584             // 128 tokens x 2 groups x 32B = 8192
#define SBARS   139776
#define SMEM_SZ 139904

#define BAR_AF    (SBARS + 0)
#define BAR_BF(s) (SBARS + 8 + 8*(s))    // B stage full
#define BAR_BE(s) (SBARS + 24 + 8*(s))   // B stage empty (256 consumer arrivals)

// ---------------------------------------------------------------------------
// Device-global scratch. Per token/code: 256 ch x 2B fp16 = 512B = 32 uint4.
// ---------------------------------------------------------------------------
__device__ __align__(128) uint4 g_ximg4[NTOK * 32];   // 8 MB fp16 slab images
__device__ __align__(128) uint4 g_cbimg4[K_ * 32];    // 4 MB fp16 chunk images
__device__ __align__(128) float g_e2h[K_];            // 0.5*||e_k||^2 exact
__device__ int4  g_cand[NTOK];                        // {i1,i2,i3, bits(gap12)}
__device__ int   g_idx[NTOK];
__device__ float g_loss;

// ---------------------------------------------------------------------------
// PTX helpers (non-'a' features only: safe for compute_103)
// ---------------------------------------------------------------------------
__device__ __forceinline__ uint32_t smem_to_u32(const void* p) {
    uint32_t a;
    asm("{ .reg .u64 t; cvta.to.shared.u64 t, %1; cvt.u32.u64 %0, t; }" : "=r"(a) : "l"(p));
    return a;
}

#define MBARRIER_INIT(addr, cnt) \
    asm volatile("mbarrier.init.shared.b64 [%0], %1;" :: "r"((uint32_t)(addr)), "r"((uint32_t)(cnt)) : "memory")

#define MBARRIER_EXPECT_TX(addr, bytes) \
    asm volatile("mbarrier.arrive.expect_tx.shared.b64 _, [%0], %1;" :: "r"((uint32_t)(addr)), "r"((uint32_t)(bytes)) : "memory")

#define MBARRIER_ARRIVE(addr) \
    asm volatile("mbarrier.arrive.shared.b64 _, [%0];" :: "r"((uint32_t)(addr)) : "memory")

#define MBARRIER_WAIT_PARITY(addr, par) do {                                     \
    uint32_t _m = (uint32_t)(addr); uint32_t _p = (uint32_t)(par); uint32_t _d;  \
    asm volatile("{\n\t.reg .pred p;\n\t"                                        \
        "mbarrier.try_wait.parity.acquire.cta.shared::cta.b64 p, [%1], %2;\n\t"  \
        "selp.b32 %0, 1, 0, p;\n\t}"                                             \
        : "=r"(_d) : "r"(_m), "r"(_p) : "memory");                               \
    if (!_d) {                                                                   \
        asm volatile("{\n\t.reg .pred P1;\n\t"                                   \
            "WL_%=:\n\t"                                                         \
            "mbarrier.try_wait.parity.acquire.cta.shared::cta.b64 P1, [%0], %1, 0x989680;\n\t" \
            "@P1 bra.uni WD_%=;\n\t"                                             \
            "bra.uni WL_%=;\n\t"                                                 \
            "WD_%=:\n\t}" :: "r"(_m), "r"(_p) : "memory");                       \
    }                                                                            \
} while (0)

__device__ __forceinline__ void bulk_g2s(uint32_t dst, const void* src, uint32_t bytes, uint32_t mbar) {
    asm volatile("cp.async.bulk.shared::cta.global.mbarrier::complete_tx::bytes [%0], [%1], %2, [%3];"
        :: "r"(dst), "l"(src), "r"(bytes), "r"(mbar) : "memory");
}

__device__ __forceinline__ void ldsm4(uint32_t addr, uint32_t r[4]) {
    asm volatile("ldmatrix.sync.aligned.m8n8.x4.shared.b16 {%0,%1,%2,%3}, [%4];"
        : "=r"(r[0]), "=r"(r[1]), "=r"(r[2]), "=r"(r[3]) : "r"(addr));
}

__device__ __forceinline__ void mma_f16(float d[4], const uint32_t a[4], uint32_t b0, uint32_t b1) {
    asm volatile("mma.sync.aligned.m16n8k16.row.col.f32.f16.f16.f32 "
        "{%0,%1,%2,%3}, {%4,%5,%6,%7}, {%8,%9}, {%0,%1,%2,%3};"
        : "+f"(d[0]), "+f"(d[1]), "+f"(d[2]), "+f"(d[3])
        : "r"(a[0]), "r"(a[1]), "r"(a[2]), "r"(a[3]), "r"(b0), "r"(b1));
}

// 8 HMMA: m32 x n32 x k16
__device__ __forceinline__ void mma_block(float acc[2][4][4],
        const uint32_t A0[4], const uint32_t A1[4],
        const uint32_t Q0[4], const uint32_t Q1[4]) {
    mma_f16(acc[0][0], A0, Q0[0], Q0[2]);
    mma_f16(acc[0][1], A0, Q0[1], Q0[3]);
    mma_f16(acc[0][2], A0, Q1[0], Q1[2]);
    mma_f16(acc[0][3], A0, Q1[1], Q1[3]);
    mma_f16(acc[1][0], A1, Q0[0], Q0[2]);
    mma_f16(acc[1][1], A1, Q0[1], Q0[3]);
    mma_f16(acc[1][2], A1, Q1[0], Q1[2]);
    mma_f16(acc[1][3], A1, Q1[1], Q1[3]);
}

__device__ __forceinline__ unsigned long long packkey(float s, int idx) {
    unsigned int b = __float_as_uint(s);
    unsigned int su = (b & 0x80000000u) ? ~b : (b | 0x80000000u);
    return ((unsigned long long)su << 32) | (unsigned int)idx;
}
__device__ __forceinline__ float unpackscore(unsigned long long k) {
    unsigned int su = (unsigned int)(k >> 32);
    unsigned int b = (su & 0x80000000u) ? (su ^ 0x80000000u) : ~su;
    return __uint_as_float(b);
}
__device__ __forceinline__ unsigned long long u64min(unsigned long long a, unsigned long long b) { return a < b ? a : b; }
__device__ __forceinline__ unsigned long long u64max(unsigned long long a, unsigned long long b) { return a > b ? a : b; }

// Merge two sorted triples -> sorted top-3 of the union.
__device__ __forceinline__ void merge3(unsigned long long& a1, unsigned long long& a2, unsigned long long& a3,
                                       unsigned long long b1, unsigned long long b2, unsigned long long b3) {
    unsigned long long n1 = u64min(a1, b1);
    unsigned long long n2 = u64min(u64max(a1, b1), u64min(a2, b2));
    unsigned long long n3 = u64min(u64min(u64max(a2, b1), u64max(a1, b2)), u64min(a3, b3));
    a1 = n1; a2 = n2; a3 = n3;
}

// pack 8 floats -> 8 fp16 in one uint4
__device__ __forceinline__ uint4 pack8h(const float* f) {
    uint32_t w[4];
#pragma unroll
    for (int p = 0; p < 4; p++) {
        __half2 h = __floats2half2_rn(f[2 * p], f[2 * p + 1]);
        w[p] = *(uint32_t*)&h;
    }
    return make_uint4(w[0], w[1], w[2], w[3]);
}

// ---------------------------------------------------------------------------
// Prep 1: codebook -> swizzled fp16 chunk images + 0.5*||e||^2 (+ zero loss).
// One warp per code row; lane l owns 16B chunk l (8 channels); phys chunk l^(r&7).
// ---------------------------------------------------------------------------
__global__ void prep_cb_kernel(const float* __restrict__ cb) {
    if (blockIdx.x == 0 && threadIdx.x == 0) g_loss = 0.0f;
    int n = (blockIdx.x * blockDim.x + threadIdx.x) >> 5;
    int l = threadIdx.x & 31;
    if (n >= K_) return;
    const float* row = cb + (size_t)n * C_;
    float f[8];
    float ss = 0.0f;
#pragma unroll
    for (int j = 0; j < 8; j++) { f[j] = row[8 * l + j]; ss += f[j] * f[j]; }
    int cid = n >> 6, r = n & 63;
    g_cbimg4[cid * 2048 + r * 32 + (l ^ (r & 7))] = pack8h(f);
#pragma unroll
    for (int o = 16; o; o >>= 1) ss += __shfl_xor_sync(0xffffffffu, ss, o);
    if (l == 0) g_e2h[n] = 0.5f * ss;
}

// ---------------------------------------------------------------------------
// Prep 2: x [B,C,H,W] -> token-major swizzled fp16 slab images.
// Grid (32, 8, 16), block (32, 8). 32(hw) x 32(c) transpose tiles.
// ---------------------------------------------------------------------------
__global__ void prep_x_kernel(const float* __restrict__ x) {
    __shared__ float tile[32][33];
    int b = blockIdx.z, hw0 = blockIdx.x * 32, c0 = blockIdx.y * 32;
    int tx = threadIdx.x, ty = threadIdx.y;
#pragma unroll
    for (int i = 0; i < 4; i++) {
        int c = c0 + ty + 8 * i;
        tile[ty + 8 * i][tx] = x[((size_t)b * C_ + c) * HW_ + hw0 + tx];
    }
    __syncthreads();
    int t = ty * 32 + tx;
    if (t < 128) {
        int hwl = t >> 2;
        int cg  = t & 3;
        float f[8];
#pragma unroll
        for (int j = 0; j < 8; j++) f[j] = tile[cg * 8 + j][hwl];
        int token = b * HW_ + hw0 + hwl;
        int slab = token >> 7, m = token & 127;
        int cchunk = (c0 >> 3) + cg;
        g_ximg4[slab * 4096 + m * 32 + (cchunk ^ (m & 7))] = pack8h(f);
    }
}

// Padding no-op so the fixed ncu capture window (-s 5 -c 1) lands on vq_main.
__global__ void noop_kernel() {}

// ---------------------------------------------------------------------------
// Main: single-pass fp16 mma.sync GEMM + per-token top-3 argmin.
// 128 CTAs x 288 threads: warps 0-7 compute (4x2 grid of m32n32), warp 8 produces.
// score = 0.5*||e||^2 - x.e  (same argmin as squared euclidean distance)
// ---------------------------------------------------------------------------
__global__ __launch_bounds__(288, 1) void vq_main_kernel() {
    extern __shared__ __align__(128) char smem[];
    uint32_t sb = smem_to_u32(smem);
    int tid = threadIdx.x;

    if (tid == 0) {
        MBARRIER_INIT(sb + BAR_AF, 1);
        MBARRIER_INIT(sb + BAR_BF(0), 1);
        MBARRIER_INIT(sb + BAR_BF(1), 1);
        MBARRIER_INIT(sb + BAR_BE(0), 256);
        MBARRIER_INIT(sb + BAR_BE(1), 256);
        asm volatile("fence.proxy.async.shared::cta;" ::: "memory");
    }
    __syncthreads();

    if (tid < 256) {
        const int l   = tid & 31;
        const int wid = tid >> 5;
        const int m0  = (wid & 3) * 32;     // token band
        const int n0w = (wid >> 2) * 32;    // code band within chunk
        const uint32_t kadd = (uint32_t)(l >> 4);
        const uint32_t swz  = (uint32_t)(l & 7);

        const uint32_t ra = (uint32_t)(m0 + (l & 15));
        uint32_t pa0 = sb + SA + ra * 512, pa1 = pa0 + 8192;
        const uint32_t rb = (uint32_t)(n0w + (l & 15));

        float bs1[4], bs2[4], bs3[4];
        int   bi1[4], bi2[4], bi3[4];
#pragma unroll
        for (int t = 0; t < 4; t++) {
            bs1[t] = 3.0e38f; bs2[t] = 3.0e38f; bs3[t] = 3.0e38f;
            bi1[t] = 0; bi2[t] = 0; bi3[t] = 0;
        }

        MBARRIER_WAIT_PARITY(sb + BAR_AF, 0);

        for (int i = 0; i < NCHUNK; i++) {
            int s = i & 1, ph = (i >> 1) & 1;
            float acc[2][4][4];
#pragma unroll
            for (int a = 0; a < 2; a++)
#pragma unroll
                for (int b = 0; b < 4; b++)
#pragma unroll
                    for (int c = 0; c < 4; c++) acc[a][b][c] = 0.0f;

            MBARRIER_WAIT_PARITY(sb + BAR_BF(s), ph);
            uint32_t pb0 = sb + SB + s * 32768 + rb * 512, pb1 = pb0 + 8192;
#pragma unroll
            for (int ks = 0; ks < 16; ks++) {
                uint32_t u = (((2u * ks + kadd) ^ swz) << 4);
                uint32_t A0[4], A1[4], Q0[4], Q1[4];
                ldsm4(pa0 + u, A0);
                ldsm4(pa1 + u, A1);
                ldsm4(pb0 + u, Q0);
                ldsm4(pb1 + u, Q1);
                mma_block(acc, A0, A1, Q0, Q1);
            }

            // epilogue: fold chunk scores into running per-token top-3
            const float* e2s = (const float*)(smem + SE2 + s * 256);
            int clbase = n0w + 2 * (l & 3);
#pragma unroll
            for (int nj = 0; nj < 4; nj++) {
#pragma unroll
                for (int col = 0; col < 2; col++) {
                    int cl = clbase + nj * 8 + col;
                    float e2v = e2s[cl];
                    int code = i * NTILE + cl;
#pragma unroll
                    for (int t = 0; t < 4; t++) {  // t = mi*2 + rowhalf
                        float sc = e2v - acc[t >> 1][nj][(t & 1) * 2 + col];
                        if (sc < bs3[t]) {
                            if (sc < bs1[t]) {
                                bs3[t] = bs2[t]; bi3[t] = bi2[t];
                                bs2[t] = bs1[t]; bi2[t] = bi1[t];
                                bs1[t] = sc;     bi1[t] = code;
                            } else if (sc < bs2[t]) {
                                bs3[t] = bs2[t]; bi3[t] = bi2[t];
                                bs2[t] = sc;     bi2[t] = code;
                            } else {
                                bs3[t] = sc;     bi3[t] = code;
                            }
                        }
                    }
                }
            }
            MBARRIER_ARRIVE(sb + BAR_BE(s));
        }

        // quad-lane merge (lanes sharing l>>2 own the same 4 token rows)
        unsigned long long k1[4], k2[4], k3[4];
#pragma unroll
        for (int t = 0; t < 4; t++) {
            k1[t] = packkey(bs1[t], bi1[t]);
            k2[t] = packkey(bs2[t], bi2[t]);
            k3[t] = packkey(bs3[t], bi3[t]);
        }
#pragma unroll
        for (int off = 1; off <= 2; off <<= 1) {
#pragma unroll
            for (int t = 0; t < 4; t++) {
                unsigned long long o1 = __shfl_xor_sync(0xffffffffu, k1[t], off);
                unsigned long long o2 = __shfl_xor_sync(0xffffffffu, k2[t], off);
                unsigned long long o3 = __shfl_xor_sync(0xffffffffu, k3[t], off);
                merge3(k1[t], k2[t], k3[t], o1, o2, o3);
            }
        }
        uint4* mrg = (uint4*)(smem + SMRG);
        if ((l & 3) == 0) {
#pragma unroll
            for (int t = 0; t < 4; t++) {
                int tok = m0 + (t >> 1) * 16 + (l >> 2) + 8 * (t & 1);
                int base = (tok * 2 + (wid >> 2)) * 2;
                mrg[base] = make_uint4(
                    (uint32_t)(k1[t] >> 32), (uint32_t)k1[t],
                    (uint32_t)(k2[t] >> 32), (uint32_t)k2[t]);
                mrg[base + 1] = make_uint4(
                    (uint32_t)(k3[t] >> 32), (uint32_t)k3[t], 0u, 0u);
            }
        }
        asm volatile("bar.sync 1, 256;" ::: "memory");
        if (tid < 128) {
            uint4 a12 = mrg[(tid * 2 + 0) * 2], a3v = mrg[(tid * 2 + 0) * 2 + 1];
            uint4 b12 = mrg[(tid * 2 + 1) * 2], b3v = mrg[(tid * 2 + 1) * 2 + 1];
            unsigned long long a1 = ((unsigned long long)a12.x << 32) | a12.y;
            unsigned long long a2 = ((unsigned long long)a12.z << 32) | a12.w;
            unsigned long long a3 = ((unsigned long long)a3v.x << 32) | a3v.y;
            unsigned long long b1 = ((unsigned long long)b12.x << 32) | b12.y;
            unsigned long long b2 = ((unsigned long long)b12.z << 32) | b12.w;
            unsigned long long b3 = ((unsigned long long)b3v.x << 32) | b3v.y;
            merge3(a1, a2, a3, b1, b2, b3);
            float gap = unpackscore(a2) - unpackscore(a1);
            g_cand[blockIdx.x * MTILE + tid] = make_int4(
                (int)(uint32_t)a1, (int)(uint32_t)a2, (int)(uint32_t)a3,
                __float_as_int(gap));
        }
    } else if (tid == 256) {
        // producer
        const char* asrc = (const char*)g_ximg4 + (size_t)blockIdx.x * 65536;
        const char* bsrc = (const char*)g_cbimg4;
        MBARRIER_EXPECT_TX(sb + BAR_AF, 65536);
        bulk_g2s(sb + SA, asrc, 32768, sb + BAR_AF);
        bulk_g2s(sb + SA + 32768, asrc + 32768, 32768, sb + BAR_AF);
        for (int i = 0; i < NCHUNK; i++) {
            int s = i & 1;
            MBARRIER_WAIT_PARITY(sb + BAR_BE(s), ((i >> 1) & 1) ^ 1);
            MBARRIER_EXPECT_TX(sb + BAR_BF(s), 32768 + 256);
            bulk_g2s(sb + SB + s * 32768, bsrc + (size_t)i * 32768, 32768, sb + BAR_BF(s));
            bulk_g2s(sb + SE2 + s * 256, (const char*)g_e2h + (size_t)i * 256, 256, sb + BAR_BF(s));
        }
    }
}

// ---------------------------------------------------------------------------
// Fixup: exact fp32 recheck of top-3 where the approx gap is small. Warp/token.
// ---------------------------------------------------------------------------
__global__ void fixup_kernel(const float* __restrict__ x, const float* __restrict__ cb) {
    int w = (blockIdx.x * blockDim.x + threadIdx.x) >> 5;
    int l = threadIdx.x & 31;
    if (w >= NTOK) return;
    int4 cd = g_cand[w];
    float gap = __int_as_float(cd.w);
    if (gap > 0.15f) { if (l == 0) g_idx[w] = cd.x; return; }
    int b = w >> 10, hw = w & (HW_ - 1);
    const float* xp = x + (size_t)b * C_ * HW_ + hw;
    const float* c1 = cb + (size_t)cd.x * C_;
    const float* c2 = cb + (size_t)cd.y * C_;
    const float* c3 = cb + (size_t)cd.z * C_;
    float d1 = 0.0f, d2 = 0.0f, d3 = 0.0f;
    for (int c = l; c < C_; c += 32) {
        float xv = xp[(size_t)c * HW_];
        d1 += xv * c1[c];
        d2 += xv * c2[c];
        d3 += xv * c3[c];
    }
#pragma unroll
    for (int o = 16; o; o >>= 1) {
        d1 += __shfl_xor_sync(0xffffffffu, d1, o);
        d2 += __shfl_xor_sync(0xffffffffu, d2, o);
        d3 += __shfl_xor_sync(0xffffffffu, d3, o);
    }
    if (l == 0) {
        float e1 = g_e2h[cd.x] - d1;
        float e2v = g_e2h[cd.y] - d2;
        float e3v = g_e2h[cd.z] - d3;
        int pick = cd.x; float bsv = e1;
        if (e2v < bsv || (e2v == bsv && cd.y < pick)) { bsv = e2v; pick = cd.y; }
        if (e3v < bsv || (e3v == bsv && cd.z < pick)) { bsv = e3v; pick = cd.z; }
        g_idx[w] = pick;
    }
}

// ---------------------------------------------------------------------------
// Gather quantized output [B,C,H,W] + MSE partial sums.
// ---------------------------------------------------------------------------
__global__ __launch_bounds__(256)
void gather_loss_kernel(const float* __restrict__ x,
                        const float* __restrict__ cb,
                        float* __restrict__ out) {
    __shared__ float warp_sums[8];
    int o = blockIdx.x * blockDim.x + threadIdx.x;
    int hw = o & (HW_ - 1);
    int bc = o >> 10;
    int c  = bc & (C_ - 1);
    int b  = bc >> 8;
    int n  = b * HW_ + hw;

    int idx  = g_idx[n];
    float q  = __ldg(&cb[(size_t)idx * C_ + c]);
    float xv = x[o];
    out[o] = q;
    float d = q - xv;
    float s = d * d;
#pragma unroll
    for (int off = 16; off; off >>= 1) s += __shfl_xor_sync(0xffffffffu, s, off);
    int lane = threadIdx.x & 31, wid = threadIdx.x >> 5;
    if (lane == 0) warp_sums[wid] = s;
    __syncthreads();
    if (wid == 0) {
        float v = (lane < 8) ? warp_sums[lane] : 0.0f;
#pragma unroll
        for (int off = 4; off; off >>= 1) v += __shfl_xor_sync(0xffffffffu, v, off);
        if (lane == 0) atomicAdd(&g_loss, v);
    }
}

__global__ void finalize_kernel(float* __restrict__ out, int out_size) {
    float m = g_loss * (1.0f / (float)NOUT);
    if (out_size >= NOUT + 1) out[NOUT] = m;
    if (out_size >= NOUT + 2) out[NOUT + 1] = m;
}

// ---------------------------------------------------------------------------
extern "C" void kernel_launch(void* const* d_in, const int* in_sizes, int n_in,
                              void* d_out, int out_size) {
    const float* x  = (const float*)d_in[0];   // [16,256,32,32]
    const float* cb = (const float*)d_in[1];   // [8192,256]
    float* out = (float*)d_out;

    cudaFuncSetAttribute(vq_main_kernel, cudaFuncAttributeMaxDynamicSharedMemorySize, SMEM_SZ);

    prep_cb_kernel<<<K_ / 8, 256>>>(cb);
    dim3 gx(32, 8, 16), bx(32, 8);
    prep_x_kernel<<<gx, bx>>>(x);
    noop_kernel<<<1, 1>>>();                               // pad: vq_main -> launch #4
    vq_main_kernel<<<NCTA, 288, SMEM_SZ>>>();
    fixup_kernel<<<NTOK / 8, 256>>>(x, cb);
    gather_loss_kernel<<<NOUT / 256, 256>>>(x, cb, out);
    finalize_kernel<<<1, 1>>>(out, out_size);
}

// round 9
// speedup vs baseline: 7.1489x; 1.0819x over previous
#include <cuda_runtime.h>
#include <cuda_fp16.h>
#include <stdint.h>

// ---------------------------------------------------------------------------
// Problem constants
// ---------------------------------------------------------------------------
#define B_   16
#define C_   256
#define HW_  1024
#define NTOK 16384                 // tokens
#define K_   8192                  // codebook entries
#define NOUT (B_ * C_ * HW_)       // 4194304

#define MTILE  128                 // tokens per CTA
#define NTILE  64                  // codes per chunk
#define NCHUNK (K_ / NTILE)        // 128
#define NCTA   (NTOK / MTILE)      // 128

// SMEM map (bytes)
#define SA      0                  // A: 128 rows x 512B (fp16)
#define SB      65536              // B: 2 stages x 32768
#define SE2     131072             // 2 stages x 256B (0.5*||e||^2 chunk)
#define SMRG    131584             // 128 tokens x 2 groups x 16B = 4096
#define SBARS   135680
#define SMEM_SZ 135808

#define BAR_AF    (SBARS + 0)
#define BAR_BF(s) (SBARS + 8 + 8*(s))    // B stage full
#define BAR_BE(s) (SBARS + 24 + 8*(s))   // B stage empty (256 consumer arrivals)

// ---------------------------------------------------------------------------
// Device-global scratch. Per token/code: 256 ch x 2B fp16 = 512B = 32 uint4.
// ---------------------------------------------------------------------------
__device__ __align__(128) uint4 g_ximg4[NTOK * 32];   // 8 MB fp16 slab images
__device__ __align__(128) uint4 g_cbimg4[K_ * 32];    // 4 MB fp16 chunk images
__device__ __align__(128) float g_e2h[K_];            // 0.5*||e_k||^2 exact
__device__ int4  g_cand[NTOK];                        // {i1, i2, bits(gap), 0}
__device__ int   g_idx[NTOK];
__device__ float g_loss;

// ---------------------------------------------------------------------------
// PTX helpers (non-'a' features only: safe for compute_103)
// ---------------------------------------------------------------------------
__device__ __forceinline__ uint32_t smem_to_u32(const void* p) {
    uint32_t a;
    asm("{ .reg .u64 t; cvta.to.shared.u64 t, %1; cvt.u32.u64 %0, t; }" : "=r"(a) : "l"(p));
    return a;
}

#define MBARRIER_INIT(addr, cnt) \
    asm volatile("mbarrier.init.shared.b64 [%0], %1;" :: "r"((uint32_t)(addr)), "r"((uint32_t)(cnt)) : "memory")

#define MBARRIER_EXPECT_TX(addr, bytes) \
    asm volatile("mbarrier.arrive.expect_tx.shared.b64 _, [%0], %1;" :: "r"((uint32_t)(addr)), "r"((uint32_t)(bytes)) : "memory")

#define MBARRIER_ARRIVE(addr) \
    asm volatile("mbarrier.arrive.shared.b64 _, [%0];" :: "r"((uint32_t)(addr)) : "memory")

#define MBARRIER_WAIT_PARITY(addr, par) do {                                     \
    uint32_t _m = (uint32_t)(addr); uint32_t _p = (uint32_t)(par); uint32_t _d;  \
    asm volatile("{\n\t.reg .pred p;\n\t"                                        \
        "mbarrier.try_wait.parity.acquire.cta.shared::cta.b64 p, [%1], %2;\n\t"  \
        "selp.b32 %0, 1, 0, p;\n\t}"                                             \
        : "=r"(_d) : "r"(_m), "r"(_p) : "memory");                               \
    if (!_d) {                                                                   \
        asm volatile("{\n\t.reg .pred P1;\n\t"                                   \
            "WL_%=:\n\t"                                                         \
            "mbarrier.try_wait.parity.acquire.cta.shared::cta.b64 P1, [%0], %1, 0x989680;\n\t" \
            "@P1 bra.uni WD_%=;\n\t"                                             \
            "bra.uni WL_%=;\n\t"                                                 \
            "WD_%=:\n\t}" :: "r"(_m), "r"(_p) : "memory");                       \
    }                                                                            \
} while (0)

__device__ __forceinline__ void bulk_g2s(uint32_t dst, const void* src, uint32_t bytes, uint32_t mbar) {
    asm volatile("cp.async.bulk.shared::cta.global.mbarrier::complete_tx::bytes [%0], [%1], %2, [%3];"
        :: "r"(dst), "l"(src), "r"(bytes), "r"(mbar) : "memory");
}

__device__ __forceinline__ void ldsm4(uint32_t addr, uint32_t r[4]) {
    asm volatile("ldmatrix.sync.aligned.m8n8.x4.shared.b16 {%0,%1,%2,%3}, [%4];"
        : "=r"(r[0]), "=r"(r[1]), "=r"(r[2]), "=r"(r[3]) : "r"(addr));
}

__device__ __forceinline__ void mma_f16(float d[4], const uint32_t a[4], uint32_t b0, uint32_t b1) {
    asm volatile("mma.sync.aligned.m16n8k16.row.col.f32.f16.f16.f32 "
        "{%0,%1,%2,%3}, {%4,%5,%6,%7}, {%8,%9}, {%0,%1,%2,%3};"
        : "+f"(d[0]), "+f"(d[1]), "+f"(d[2]), "+f"(d[3])
        : "r"(a[0]), "r"(a[1]), "r"(a[2]), "r"(a[3]), "r"(b0), "r"(b1));
}

// 8 HMMA: m32 x n32 x k16
__device__ __forceinline__ void mma_block(float acc[2][4][4],
        const uint32_t A0[4], const uint32_t A1[4],
        const uint32_t Q0[4], const uint32_t Q1[4]) {
    mma_f16(acc[0][0], A0, Q0[0], Q0[2]);
    mma_f16(acc[0][1], A0, Q0[1], Q0[3]);
    mma_f16(acc[0][2], A0, Q1[0], Q1[2]);
    mma_f16(acc[0][3], A0, Q1[1], Q1[3]);
    mma_f16(acc[1][0], A1, Q0[0], Q0[2]);
    mma_f16(acc[1][1], A1, Q0[1], Q0[3]);
    mma_f16(acc[1][2], A1, Q1[0], Q1[2]);
    mma_f16(acc[1][3], A1, Q1[1], Q1[3]);
}

__device__ __forceinline__ unsigned long long packkey(float s, int idx) {
    unsigned int b = __float_as_uint(s);
    unsigned int su = (b & 0x80000000u) ? ~b : (b | 0x80000000u);
    return ((unsigned long long)su << 32) | (unsigned int)idx;
}
__device__ __forceinline__ float unpackscore(unsigned long long k) {
    unsigned int su = (unsigned int)(k >> 32);
    unsigned int b = (su & 0x80000000u) ? (su ^ 0x80000000u) : ~su;
    return __uint_as_float(b);
}
__device__ __forceinline__ unsigned long long u64min(unsigned long long a, unsigned long long b) { return a < b ? a : b; }
__device__ __forceinline__ unsigned long long u64max(unsigned long long a, unsigned long long b) { return a > b ? a : b; }

// pack 8 floats -> 8 fp16 in one uint4
__device__ __forceinline__ uint4 pack8h(const float* f) {
    uint32_t w[4];
#pragma unroll
    for (int p = 0; p < 4; p++) {
        __half2 h = __floats2half2_rn(f[2 * p], f[2 * p + 1]);
        w[p] = *(uint32_t*)&h;
    }
    return make_uint4(w[0], w[1], w[2], w[3]);
}

// ---------------------------------------------------------------------------
// Prep 1: codebook -> swizzled fp16 chunk images + 0.5*||e||^2 (+ zero loss).
// ---------------------------------------------------------------------------
__global__ void prep_cb_kernel(const float* __restrict__ cb) {
    if (blockIdx.x == 0 && threadIdx.x == 0) g_loss = 0.0f;
    int n = (blockIdx.x * blockDim.x + threadIdx.x) >> 5;
    int l = threadIdx.x & 31;
    if (n >= K_) return;
    const float* row = cb + (size_t)n * C_;
    float f[8];
    float ss = 0.0f;
#pragma unroll
    for (int j = 0; j < 8; j++) { f[j] = row[8 * l + j]; ss += f[j] * f[j]; }
    int cid = n >> 6, r = n & 63;
    g_cbimg4[cid * 2048 + r * 32 + (l ^ (r & 7))] = pack8h(f);
#pragma unroll
    for (int o = 16; o; o >>= 1) ss += __shfl_xor_sync(0xffffffffu, ss, o);
    if (l == 0) g_e2h[n] = 0.5f * ss;
}

// ---------------------------------------------------------------------------
// Prep 2: x [B,C,H,W] -> token-major swizzled fp16 slab images.
// ---------------------------------------------------------------------------
__global__ void prep_x_kernel(const float* __restrict__ x) {
    __shared__ float tile[32][33];
    int b = blockIdx.z, hw0 = blockIdx.x * 32, c0 = blockIdx.y * 32;
    int tx = threadIdx.x, ty = threadIdx.y;
#pragma unroll
    for (int i = 0; i < 4; i++) {
        int c = c0 + ty + 8 * i;
        tile[ty + 8 * i][tx] = x[((size_t)b * C_ + c) * HW_ + hw0 + tx];
    }
    __syncthreads();
    int t = ty * 32 + tx;
    if (t < 128) {
        int hwl = t >> 2;
        int cg  = t & 3;
        float f[8];
#pragma unroll
        for (int j = 0; j < 8; j++) f[j] = tile[cg * 8 + j][hwl];
        int token = b * HW_ + hw0 + hwl;
        int slab = token >> 7, m = token & 127;
        int cchunk = (c0 >> 3) + cg;
        g_ximg4[slab * 4096 + m * 32 + (cchunk ^ (m & 7))] = pack8h(f);
    }
}

// Padding no-op so the fixed ncu capture window (-s 5 -c 1) lands on vq_main.
__global__ void noop_kernel() {}

// ---------------------------------------------------------------------------
// Main: single-pass fp16 mma.sync GEMM + per-token top-2 argmin.
// 128 CTAs x 288 threads: warps 0-7 compute (4x2 grid of m32n32), warp 8 produces.
// Epilogue per 8-score group: min-tree, rare sorted-insert.
// score = 0.5*||e||^2 - x.e  (same argmin as squared euclidean distance)
// ---------------------------------------------------------------------------
__global__ __launch_bounds__(288, 1) void vq_main_kernel() {
    extern __shared__ __align__(128) char smem[];
    uint32_t sb = smem_to_u32(smem);
    int tid = threadIdx.x;

    if (tid == 0) {
        MBARRIER_INIT(sb + BAR_AF, 1);
        MBARRIER_INIT(sb + BAR_BF(0), 1);
        MBARRIER_INIT(sb + BAR_BF(1), 1);
        MBARRIER_INIT(sb + BAR_BE(0), 256);
        MBARRIER_INIT(sb + BAR_BE(1), 256);
        asm volatile("fence.proxy.async.shared::cta;" ::: "memory");
    }
    __syncthreads();

    if (tid < 256) {
        const int l   = tid & 31;
        const int wid = tid >> 5;
        const int m0  = (wid & 3) * 32;     // token band
        const int n0w = (wid >> 2) * 32;    // code band within chunk
        const uint32_t kadd = (uint32_t)(l >> 4);
        const uint32_t swz  = (uint32_t)(l & 7);

        const uint32_t ra = (uint32_t)(m0 + (l & 15));
        uint32_t pa0 = sb + SA + ra * 512, pa1 = pa0 + 8192;
        const uint32_t rb = (uint32_t)(n0w + (l & 15));

        float bs1[4], bs2[4];
        int   bi1[4], bi2[4];
#pragma unroll
        for (int t = 0; t < 4; t++) { bs1[t] = 3.0e38f; bs2[t] = 3.0e38f; bi1[t] = 0; bi2[t] = 0; }

        MBARRIER_WAIT_PARITY(sb + BAR_AF, 0);

        for (int i = 0; i < NCHUNK; i++) {
            int s = i & 1, ph = (i >> 1) & 1;
            float acc[2][4][4];
#pragma unroll
            for (int a = 0; a < 2; a++)
#pragma unroll
                for (int b = 0; b < 4; b++)
#pragma unroll
                    for (int c = 0; c < 4; c++) acc[a][b][c] = 0.0f;

            MBARRIER_WAIT_PARITY(sb + BAR_BF(s), ph);
            uint32_t pb0 = sb + SB + s * 32768 + rb * 512, pb1 = pb0 + 8192;

            // explicit double-buffered fragment pipeline over 16 k-steps
            uint32_t A0[2][4], A1[2][4], Q0[2][4], Q1[2][4];
            {
                uint32_t u = ((kadd ^ swz) << 4);
                ldsm4(pa0 + u, A0[0]);
                ldsm4(pa1 + u, A1[0]);
                ldsm4(pb0 + u, Q0[0]);
                ldsm4(pb1 + u, Q1[0]);
            }
#pragma unroll
            for (int ks = 0; ks < 16; ks++) {
                int cur = ks & 1, nxt = cur ^ 1;
                if (ks < 15) {
                    uint32_t u = (((2u * (ks + 1) + kadd) ^ swz) << 4);
                    ldsm4(pa0 + u, A0[nxt]);
                    ldsm4(pa1 + u, A1[nxt]);
                    ldsm4(pb0 + u, Q0[nxt]);
                    ldsm4(pb1 + u, Q1[nxt]);
                }
                mma_block(acc, A0[cur], A1[cur], Q0[cur], Q1[cur]);
            }

            // epilogue: min-tree per 8-score group, rare top-2 insert
            const float* e2s = (const float*)(smem + SE2 + s * 256);
            int clbase = n0w + 2 * (l & 3);
#pragma unroll
            for (int t = 0; t < 4; t++) {          // t = mi*2 + rowhalf
                float sc[8];
#pragma unroll
                for (int j = 0; j < 8; j++) {
                    int cl = clbase + (j >> 1) * 8 + (j & 1);
                    sc[j] = e2s[cl] - acc[t >> 1][j >> 1][(t & 1) * 2 + (j & 1)];
                }
                float m01 = fminf(sc[0], sc[1]), m23 = fminf(sc[2], sc[3]);
                float m45 = fminf(sc[4], sc[5]), m67 = fminf(sc[6], sc[7]);
                float mm = fminf(fminf(m01, m23), fminf(m45, m67));
                if (mm < bs2[t]) {
#pragma unroll
                    for (int j = 0; j < 8; j++) {   // ascending code order: ties -> lowest idx
                        int code = i * NTILE + clbase + (j >> 1) * 8 + (j & 1);
                        float v = sc[j];
                        if (v < bs1[t])      { bs2[t] = bs1[t]; bi2[t] = bi1[t]; bs1[t] = v; bi1[t] = code; }
                        else if (v < bs2[t]) { bs2[t] = v; bi2[t] = code; }
                    }
                }
            }
            MBARRIER_ARRIVE(sb + BAR_BE(s));
        }

        // quad-lane merge (lanes sharing l>>2 own the same 4 token rows)
        unsigned long long k1[4], k2[4];
#pragma unroll
        for (int t = 0; t < 4; t++) { k1[t] = packkey(bs1[t], bi1[t]); k2[t] = packkey(bs2[t], bi2[t]); }
#pragma unroll
        for (int off = 1; off <= 2; off <<= 1) {
#pragma unroll
            for (int t = 0; t < 4; t++) {
                unsigned long long o1 = __shfl_xor_sync(0xffffffffu, k1[t], off);
                unsigned long long o2 = __shfl_xor_sync(0xffffffffu, k2[t], off);
                unsigned long long n1 = u64min(k1[t], o1);
                unsigned long long n2 = u64min(u64max(k1[t], o1), u64min(k2[t], o2));
                k1[t] = n1; k2[t] = n2;
            }
        }
        uint4* mrg = (uint4*)(smem + SMRG);
        if ((l & 3) == 0) {
#pragma unroll
            for (int t = 0; t < 4; t++) {
                int tok = m0 + (t >> 1) * 16 + (l >> 2) + 8 * (t & 1);
                mrg[tok * 2 + (wid >> 2)] = make_uint4(
                    (uint32_t)(k1[t] >> 32), (uint32_t)k1[t],
                    (uint32_t)(k2[t] >> 32), (uint32_t)k2[t]);
            }
        }
        asm volatile("bar.sync 1, 256;" ::: "memory");
        if (tid < 128) {
            uint4 a = mrg[tid * 2], b = mrg[tid * 2 + 1];
            unsigned long long a1 = ((unsigned long long)a.x << 32) | a.y;
            unsigned long long a2 = ((unsigned long long)a.z << 32) | a.w;
            unsigned long long b1 = ((unsigned long long)b.x << 32) | b.y;
            unsigned long long b2 = ((unsigned long long)b.z << 32) | b.w;
            unsigned long long m1 = u64min(a1, b1);
            unsigned long long m2 = u64min(u64max(a1, b1), u64min(a2, b2));
            float gap = unpackscore(m2) - unpackscore(m1);
            g_cand[blockIdx.x * MTILE + tid] = make_int4(
                (int)(uint32_t)m1, (int)(uint32_t)m2, __float_as_int(gap), 0);
        }
    } else if (tid == 256) {
        // producer
        const char* asrc = (const char*)g_ximg4 + (size_t)blockIdx.x * 65536;
        const char* bsrc = (const char*)g_cbimg4;
        MBARRIER_EXPECT_TX(sb + BAR_AF, 65536);
        bulk_g2s(sb + SA, asrc, 32768, sb + BAR_AF);
        bulk_g2s(sb + SA + 32768, asrc + 32768, 32768, sb + BAR_AF);
        for (int i = 0; i < NCHUNK; i++) {
            int s = i & 1;
            MBARRIER_WAIT_PARITY(sb + BAR_BE(s), ((i >> 1) & 1) ^ 1);
            MBARRIER_EXPECT_TX(sb + BAR_BF(s), 32768 + 256);
            bulk_g2s(sb + SB + s * 32768, bsrc + (size_t)i * 32768, 32768, sb + BAR_BF(s));
            bulk_g2s(sb + SE2 + s * 256, (const char*)g_e2h + (size_t)i * 256, 256, sb + BAR_BF(s));
        }
    }
}

// ---------------------------------------------------------------------------
// Fixup: exact fp32 recheck of top-2 where the approx gap is small. Warp/token.
// ---------------------------------------------------------------------------
__global__ void fixup_kernel(const float* __restrict__ x, const float* __restrict__ cb) {
    int w = (blockIdx.x * blockDim.x + threadIdx.x) >> 5;
    int l = threadIdx.x & 31;
    if (w >= NTOK) return;
    int4 cd = g_cand[w];
    float gap = __int_as_float(cd.z);
    if (gap > 0.15f) { if (l == 0) g_idx[w] = cd.x; return; }
    int b = w >> 10, hw = w & (HW_ - 1);
    const float* xp = x + (size_t)b * C_ * HW_ + hw;
    const float* c1 = cb + (size_t)cd.x * C_;
    const float* c2 = cb + (size_t)cd.y * C_;
    float d1 = 0.0f, d2 = 0.0f;
    for (int c = l; c < C_; c += 32) {
        float xv = xp[(size_t)c * HW_];
        d1 += xv * c1[c];
        d2 += xv * c2[c];
    }
#pragma unroll
    for (int o = 16; o; o >>= 1) {
        d1 += __shfl_xor_sync(0xffffffffu, d1, o);
        d2 += __shfl_xor_sync(0xffffffffu, d2, o);
    }
    if (l == 0) {
        float e1 = g_e2h[cd.x] - d1, e2v = g_e2h[cd.y] - d2;
        int pick = cd.x;
        if (e2v < e1 || (e2v == e1 && cd.y < cd.x)) pick = cd.y;
        g_idx[w] = pick;
    }
}

// ---------------------------------------------------------------------------
// Gather quantized output [B,C,H,W] + MSE partial sums.
// ---------------------------------------------------------------------------
__global__ __launch_bounds__(256)
void gather_loss_kernel(const float* __restrict__ x,
                        const float* __restrict__ cb,
                        float* __restrict__ out) {
    __shared__ float warp_sums[8];
    int o = blockIdx.x * blockDim.x + threadIdx.x;
    int hw = o & (HW_ - 1);
    int bc = o >> 10;
    int c  = bc & (C_ - 1);
    int b  = bc >> 8;
    int n  = b * HW_ + hw;

    int idx  = g_idx[n];
    float q  = __ldg(&cb[(size_t)idx * C_ + c]);
    float xv = x[o];
    out[o] = q;
    float d = q - xv;
    float s = d * d;
#pragma unroll
    for (int off = 16; off; off >>= 1) s += __shfl_xor_sync(0xffffffffu, s, off);
    int lane = threadIdx.x & 31, wid = threadIdx.x >> 5;
    if (lane == 0) warp_sums[wid] = s;
    __syncthreads();
    if (wid == 0) {
        float v = (lane < 8) ? warp_sums[lane] : 0.0f;
#pragma unroll
        for (int off = 4; off; off >>= 1) v += __shfl_xor_sync(0xffffffffu, v, off);
        if (lane == 0) atomicAdd(&g_loss, v);
    }
}

__global__ void finalize_kernel(float* __restrict__ out, int out_size) {
    float m = g_loss * (1.0f / (float)NOUT);
    if (out_size >= NOUT + 1) out[NOUT] = m;
    if (out_size >= NOUT + 2) out[NOUT + 1] = m;
}

// ---------------------------------------------------------------------------
extern "C" void kernel_launch(void* const* d_in, const int* in_sizes, int n_in,
                              void* d_out, int out_size) {
    const float* x  = (const float*)d_in[0];   // [16,256,32,32]
    const float* cb = (const float*)d_in[1];   // [8192,256]
    float* out = (float*)d_out;

    cudaFuncSetAttribute(vq_main_kernel, cudaFuncAttributeMaxDynamicSharedMemorySize, SMEM_SZ);

    prep_cb_kernel<<<K_ / 8, 256>>>(cb);
    dim3 gx(32, 8, 16), bx(32, 8);
    prep_x_kernel<<<gx, bx>>>(x);
    noop_kernel<<<1, 1>>>();                               // pad: vq_main -> launch #4
    vq_main_kernel<<<NCTA, 288, SMEM_SZ>>>();
    fixup_kernel<<<NTOK / 8, 256>>>(x, cb);
    gather_loss_kernel<<<NOUT / 256, 256>>>(x, cb, out);
    finalize_kernel<<<1, 1>>>(out, out_size);
}